// round 13
// baseline (speedup 1.0000x reference)
#include <cuda_runtime.h>
#include <cuda_bf16.h>
#include <cstdint>

#define D 64
#define MAXN 100000

// Scratch accumulator g[N, 64] (static __device__: no allocs allowed)
__device__ __align__(16) float g_scratch[MAXN * D];

// ---------------------------------------------------------------------------
// Scatter:  g[dst[e], :] += (ci[src[e]] * drop_mask[e]) * review_feat[e, :]
// Warp-cooperative; ballot skips ~70% exact-zero dropout edges.
// NEW: 4 live edges per iteration (8 lanes each, 2 float4 per lane):
// half the loop iterations/shuffles, 2x per-iter MLP. Per-edge inst count
// unchanged (2 LDG.128 + 2 RED.128 warp-inst per 4 edges).
// ---------------------------------------------------------------------------
__global__ void scatter_kernel(const float4* __restrict__ rf,
                               const float*  __restrict__ ci,
                               const float*  __restrict__ dm,
                               const int*    __restrict__ src,
                               const int*    __restrict__ dst,
                               int E) {
    int warp = (blockIdx.x * blockDim.x + threadIdx.x) >> 5;
    int lane = threadIdx.x & 31;
    int ebase = warp * 32;
    int e = ebase + lane;

    float m = 0.f, s = 0.f;
    int d = 0;
    if (e < E) {
        m = dm[e];
        if (m != 0.f) {
            d = dst[e];
            s = ci[src[e]] * m;
        }
    }
    unsigned mask = __ballot_sync(0xFFFFFFFFu, m != 0.f);

    int g4 = lane >> 3;                  // group 0..3: which live edge
    int q8 = lane & 7;                   // 8 lanes per edge, 2 float4 each

    while (mask) {
        int l[4];
        #pragma unroll
        for (int j = 0; j < 4; j++) {
            l[j] = mask ? (__ffs(mask) - 1) : -1;
            if (mask) mask &= mask - 1;
        }
        int myl = l[g4];
        int lsel = (myl >= 0) ? myl : l[0];
        float sv = __shfl_sync(0xFFFFFFFFu, s, lsel);
        int   dv = __shfl_sync(0xFFFFFFFFu, d, lsel);

        if (myl >= 0) {
            size_t rbase = (size_t)(ebase + myl) * 16 + q8 * 2;
            float4 v0 = rf[rbase];
            float4 v1 = rf[rbase + 1];
            v0.x *= sv; v0.y *= sv; v0.z *= sv; v0.w *= sv;
            v1.x *= sv; v1.y *= sv; v1.z *= sv; v1.w *= sv;
            float* p = &g_scratch[(size_t)dv * D + q8 * 8];
            asm volatile("red.global.add.v4.f32 [%0], {%1, %2, %3, %4};"
                         :: "l"(p), "f"(v0.x), "f"(v0.y), "f"(v0.z), "f"(v0.w)
                         : "memory");
            asm volatile("red.global.add.v4.f32 [%0], {%1, %2, %3, %4};"
                         :: "l"(p + 4), "f"(v1.x), "f"(v1.y), "f"(v1.z), "f"(v1.w)
                         : "memory");
        }
    }
}

// ===========================================================================
// HMMA GEMM: out = (g @ W^T) * ci, fp32 via bf16 Karatsuba 3-pass split.
// Block: 256 thr = 8 warps; tile 256 rows x 64 cols.
// Warp: 64 rows x 32 cols (4 row-quads x 2 col-halves) -> B fragment reuse 4x.
// kc-outer loop: B frags (hi+lo, 4 n-octets) in 16 regs; A stripes inner.
// smem rows 128B, 16B-chunk XOR swizzle (c ^= row&7) -> conflict-free ldmatrix.
// ===========================================================================
#define SM_WHI 0
#define SM_WLO 8192
#define SM_AHI 16384
#define SM_ALO 49152
#define SM_TOTAL 81920

__device__ __forceinline__ uint32_t smem_u32(const void* p) {
    uint32_t a;
    asm("{ .reg .u64 t; cvta.to.shared.u64 t, %1; cvt.u32.u64 %0, t; }"
        : "=r"(a) : "l"(p));
    return a;
}
__device__ __forceinline__ void ldsm_x4(uint32_t& r0, uint32_t& r1,
                                        uint32_t& r2, uint32_t& r3, uint32_t a) {
    asm volatile("ldmatrix.sync.aligned.m8n8.x4.shared.b16 {%0,%1,%2,%3}, [%4];"
                 : "=r"(r0), "=r"(r1), "=r"(r2), "=r"(r3) : "r"(a));
}
__device__ __forceinline__ void mma_bf16(float* d, const uint32_t* a,
                                         uint32_t b0, uint32_t b1) {
    asm volatile("mma.sync.aligned.m16n8k16.row.col.f32.bf16.bf16.f32 "
                 "{%0,%1,%2,%3}, {%4,%5,%6,%7}, {%8,%9}, {%0,%1,%2,%3};"
                 : "+f"(d[0]), "+f"(d[1]), "+f"(d[2]), "+f"(d[3])
                 : "r"(a[0]), "r"(a[1]), "r"(a[2]), "r"(a[3]),
                   "r"(b0), "r"(b1));
}
__device__ __forceinline__ void split4(const float4& x, uint2& hv, uint2& lv) {
    __nv_bfloat162 h01 = __float22bfloat162_rn(make_float2(x.x, x.y));
    __nv_bfloat162 h23 = __float22bfloat162_rn(make_float2(x.z, x.w));
    float2 f01 = __bfloat1622float2(h01);
    float2 f23 = __bfloat1622float2(h23);
    __nv_bfloat162 l01 = __float22bfloat162_rn(make_float2(x.x - f01.x, x.y - f01.y));
    __nv_bfloat162 l23 = __float22bfloat162_rn(make_float2(x.z - f23.x, x.w - f23.y));
    hv.x = *reinterpret_cast<uint32_t*>(&h01);
    hv.y = *reinterpret_cast<uint32_t*>(&h23);
    lv.x = *reinterpret_cast<uint32_t*>(&l01);
    lv.y = *reinterpret_cast<uint32_t*>(&l23);
}

__global__ void __launch_bounds__(256, 2)
gemm_mma_kernel(const float* __restrict__ W, const float* __restrict__ ci,
                float* __restrict__ out, int N) {
    extern __shared__ __align__(1024) char smem[];
    uint32_t sb = smem_u32(smem);
    int tid = threadIdx.x, w = tid >> 5, lane = tid & 31;
    int row0 = blockIdx.x * 256;

    // ---- convert W -> bf16 hi/lo, swizzled 16B chunks (512 chunks) ----
    #pragma unroll
    for (int i = tid; i < 512; i += 256) {
        int f = i >> 3, c = i & 7;
        const float4* wp = reinterpret_cast<const float4*>(W) + f * 16 + c * 2;
        float4 x0 = wp[0], x1 = wp[1];
        uint2 h0, l0, h1, l1;
        split4(x0, h0, l0);
        split4(x1, h1, l1);
        uint32_t off = (uint32_t)f * 128 + (uint32_t)((c ^ (f & 7)) << 4);
        *reinterpret_cast<uint4*>(smem + SM_WHI + off) = make_uint4(h0.x, h0.y, h1.x, h1.y);
        *reinterpret_cast<uint4*>(smem + SM_WLO + off) = make_uint4(l0.x, l0.y, l1.x, l1.y);
    }
    // ---- convert g tile [256][64] -> bf16 hi/lo, swizzled (2048 chunks) ----
    #pragma unroll
    for (int i = tid; i < 2048; i += 256) {
        int r = i >> 3, c = i & 7;
        int row = row0 + r;
        float4 x0, x1;
        if (row < N) {
            const float4* gp = reinterpret_cast<const float4*>(g_scratch)
                             + (size_t)row * 16 + c * 2;
            x0 = gp[0]; x1 = gp[1];
        } else {
            x0 = make_float4(0.f, 0.f, 0.f, 0.f);
            x1 = x0;
        }
        uint2 h0, l0, h1, l1;
        split4(x0, h0, l0);
        split4(x1, h1, l1);
        uint32_t off = (uint32_t)r * 128 + (uint32_t)((c ^ (r & 7)) << 4);
        *reinterpret_cast<uint4*>(smem + SM_AHI + off) = make_uint4(h0.x, h0.y, h1.x, h1.y);
        *reinterpret_cast<uint4*>(smem + SM_ALO + off) = make_uint4(l0.x, l0.y, l1.x, l1.y);
    }
    __syncthreads();

    int ch = w & 1;             // column half: cols ch*32 .. +31
    int rq = w >> 1;            // row quad:    rows rq*64 .. +63 (block-local)

    // A ldmatrix lane plan (proven in round 12): lanes 0-7 rows+0..7 klo,
    // 8-15 rows+8..15 klo, 16-23 rows+0..7 khi, 24-31 rows+8..15 khi.
    int i8 = lane & 7;
    int halfrow = (lane >> 3) & 1;
    int kpart = lane >> 4;
    // B ldmatrix.x4 lane plan: m0 = n-octet0 klo, m1 = octet0 khi,
    // m2 = octet1 klo, m3 = octet1 khi  =>  (b0,b1) nb even, (b2,b3) nb odd.
    int bn_off = ((lane >> 4) & 1) * 8 + (lane & 7);
    int bkp = (lane >> 3) & 1;

    float acc[4][4][4];         // [stripe][nb][frag]
    #pragma unroll
    for (int st = 0; st < 4; st++)
        #pragma unroll
        for (int nb = 0; nb < 4; nb++)
            #pragma unroll
            for (int j = 0; j < 4; j++) acc[st][nb][j] = 0.f;

    #pragma unroll
    for (int kc = 0; kc < 4; kc++) {
        // B fragments for this kc: hi+lo, both n-octet pairs (16 regs)
        uint32_t BH[2][4], BL[2][4];
        #pragma unroll
        for (int nbp = 0; nbp < 2; nbp++) {
            int n = ch * 32 + nbp * 16 + bn_off;
            uint32_t chunk = (uint32_t)(2 * kc + bkp);
            uint32_t off = (uint32_t)n * 128 + ((chunk ^ (uint32_t)(n & 7)) << 4);
            ldsm_x4(BH[nbp][0], BH[nbp][1], BH[nbp][2], BH[nbp][3], sb + SM_WHI + off);
            ldsm_x4(BL[nbp][0], BL[nbp][1], BL[nbp][2], BL[nbp][3], sb + SM_WLO + off);
        }
        #pragma unroll
        for (int st = 0; st < 4; st++) {
            int arow = rq * 64 + st * 16 + halfrow * 8 + i8;
            uint32_t achunk = (uint32_t)(2 * kc + kpart);
            uint32_t aoff = (uint32_t)arow * 128
                          + ((achunk ^ (uint32_t)(arow & 7)) << 4);
            uint32_t AH[4], AL[4];
            ldsm_x4(AH[0], AH[1], AH[2], AH[3], sb + SM_AHI + aoff);
            ldsm_x4(AL[0], AL[1], AL[2], AL[3], sb + SM_ALO + aoff);
            #pragma unroll
            for (int nbp = 0; nbp < 2; nbp++) {
                mma_bf16(acc[st][2 * nbp],     AH, BH[nbp][0], BH[nbp][1]); // hi*hi
                mma_bf16(acc[st][2 * nbp + 1], AH, BH[nbp][2], BH[nbp][3]);
                mma_bf16(acc[st][2 * nbp],     AH, BL[nbp][0], BL[nbp][1]); // hi*lo
                mma_bf16(acc[st][2 * nbp + 1], AH, BL[nbp][2], BL[nbp][3]);
                mma_bf16(acc[st][2 * nbp],     AL, BH[nbp][0], BH[nbp][1]); // lo*hi
                mma_bf16(acc[st][2 * nbp + 1], AL, BH[nbp][2], BH[nbp][3]);
            }
        }
    }

    // ---- epilogue: scale by ci[row], float2 stores ----
    int group = lane >> 2, tig = lane & 3;
    #pragma unroll
    for (int st = 0; st < 4; st++) {
        int rA = row0 + rq * 64 + st * 16 + group;
        int rB = rA + 8;
        float cA = (rA < N) ? ci[rA] : 0.f;
        float cB = (rB < N) ? ci[rB] : 0.f;
        #pragma unroll
        for (int nb = 0; nb < 4; nb++) {
            int col = ch * 32 + nb * 8 + 2 * tig;
            if (rA < N) {
                float2 v = make_float2(acc[st][nb][0] * cA, acc[st][nb][1] * cA);
                *reinterpret_cast<float2*>(&out[(size_t)rA * D + col]) = v;
            }
            if (rB < N) {
                float2 v = make_float2(acc[st][nb][2] * cB, acc[st][nb][3] * cB);
                *reinterpret_cast<float2*>(&out[(size_t)rB * D + col]) = v;
            }
        }
    }
}

// ---------------------------------------------------------------------------
// Launch
// Inputs: review_feat [E,64] f32, ci [N,1] f32, W [64,64] f32,
//         drop_mask [E,1] f32, src [E] i32, dst [E] i32.  Output: [N,64] f32
// ---------------------------------------------------------------------------
extern "C" void kernel_launch(void* const* d_in, const int* in_sizes, int n_in,
                              void* d_out, int out_size) {
    const float4* rf  = (const float4*)d_in[0];
    const float*  ci  = (const float*) d_in[1];
    const float*  W   = (const float*) d_in[2];
    const float*  dm  = (const float*) d_in[3];
    const int*    src = (const int*)   d_in[4];
    const int*    dst = (const int*)   d_in[5];
    float* out = (float*)d_out;

    int E = in_sizes[4];
    int N = in_sizes[1];

    // 1. zero scratch accumulator (graph-capturable memset node)
    void* gptr = nullptr;
    cudaGetSymbolAddress(&gptr, g_scratch);
    cudaMemsetAsync(gptr, 0, (size_t)N * D * sizeof(float), 0);

    // 2. warp-cooperative scatter-accumulate (dropout-sparse, REDG.v4)
    int warps = (E + 31) / 32;
    int sblocks = (warps * 32 + 255) / 256;
    scatter_kernel<<<sblocks, 256>>>(rf, ci, dm, src, dst, E);

    // 3. HMMA GEMM (bf16 3-pass split) fused with ci scale
    int gblocks = (N + 255) / 256;
    cudaFuncSetAttribute(gemm_mma_kernel,
                         cudaFuncAttributeMaxDynamicSharedMemorySize, SM_TOTAL);
    gemm_mma_kernel<<<gblocks, 256, SM_TOTAL>>>(W, ci, out, N);
}

// round 14
// speedup vs baseline: 1.0006x; 1.0006x over previous
#include <cuda_runtime.h>
#include <cuda_bf16.h>
#include <cstdint>

#define D 64
#define MAXN 100000

// Scratch accumulator g[N, 64] (static __device__: no allocs allowed)
__device__ __align__(16) float g_scratch[MAXN * D];

// ---------------------------------------------------------------------------
// Scatter:  g[dst[e], :] += (ci[src[e]] * drop_mask[e]) * review_feat[e, :]
// Round-12 proven form (~28us, near LTS-capacity floor): coalesced metadata,
// ballot skips ~70% exact-zero dropout edges, 2 live edges/iter,
// LDG.128 + red.global.add.v4.f32.
// ---------------------------------------------------------------------------
__global__ void scatter_kernel(const float4* __restrict__ rf,
                               const float*  __restrict__ ci,
                               const float*  __restrict__ dm,
                               const int*    __restrict__ src,
                               const int*    __restrict__ dst,
                               int E) {
    int warp = (blockIdx.x * blockDim.x + threadIdx.x) >> 5;
    int lane = threadIdx.x & 31;
    int ebase = warp * 32;
    int e = ebase + lane;

    float m = 0.f, s = 0.f;
    int d = 0;
    if (e < E) {
        m = dm[e];
        if (m != 0.f) {
            d = dst[e];
            s = ci[src[e]] * m;
        }
    }
    unsigned mask = __ballot_sync(0xFFFFFFFFu, m != 0.f);

    int half = lane >> 4;
    int q = lane & 15;

    while (mask) {
        int l0 = __ffs(mask) - 1; mask &= mask - 1;
        int l1 = -1;
        if (mask) { l1 = __ffs(mask) - 1; mask &= mask - 1; }

        int l = half ? l1 : l0;
        int lsafe = (l >= 0) ? l : l0;
        float sv = __shfl_sync(0xFFFFFFFFu, s, lsafe);
        int   dv = __shfl_sync(0xFFFFFFFFu, d, lsafe);

        if (l >= 0) {
            float4 v = rf[(size_t)(ebase + l) * 16 + q];
            v.x *= sv; v.y *= sv; v.z *= sv; v.w *= sv;
            float* p = &g_scratch[(size_t)dv * D + q * 4];
            asm volatile("red.global.add.v4.f32 [%0], {%1, %2, %3, %4};"
                         :: "l"(p), "f"(v.x), "f"(v.y), "f"(v.z), "f"(v.w)
                         : "memory");
        }
    }
}

// ===========================================================================
// HMMA GEMM: out = (g @ W^T) * ci, fp32 via bf16 Karatsuba 3-pass split.
// Round-12 block shape (128 rows x 64 cols, 8 warps, warp = 16 rows), but the
// A path now loads mma fragments DIRECTLY from g_scratch (L2-resident) with
// LDG.64 -- the m16n8k16 A layout is 2 consecutive floats per register:
//   rows lane>>2 and +8, k = (lane&3)*2 and +8 -- then bf16-splits in regs.
// Deletes A staging (LDG loop, 2xSTS, 2xldmatrix) => ~half the L1 wavefronts.
// B stays in smem via the proven swizzled ldmatrix.x2 path; smem = W only.
// ===========================================================================
__device__ __forceinline__ uint32_t smem_u32(const void* p) {
    uint32_t a;
    asm("{ .reg .u64 t; cvta.to.shared.u64 t, %1; cvt.u32.u64 %0, t; }"
        : "=r"(a) : "l"(p));
    return a;
}
__device__ __forceinline__ void ldsm_x2(uint32_t& r0, uint32_t& r1, uint32_t a) {
    asm volatile("ldmatrix.sync.aligned.m8n8.x2.shared.b16 {%0,%1}, [%2];"
                 : "=r"(r0), "=r"(r1) : "r"(a));
}
__device__ __forceinline__ void mma_bf16(float* d, const uint32_t* a,
                                         uint32_t b0, uint32_t b1) {
    asm volatile("mma.sync.aligned.m16n8k16.row.col.f32.bf16.bf16.f32 "
                 "{%0,%1,%2,%3}, {%4,%5,%6,%7}, {%8,%9}, {%0,%1,%2,%3};"
                 : "+f"(d[0]), "+f"(d[1]), "+f"(d[2]), "+f"(d[3])
                 : "r"(a[0]), "r"(a[1]), "r"(a[2]), "r"(a[3]),
                   "r"(b0), "r"(b1));
}
// split float2 -> packed bf16x2 hi and lo
__device__ __forceinline__ void split2(float2 x, uint32_t& h, uint32_t& l) {
    __nv_bfloat162 h2 = __float22bfloat162_rn(x);
    float2 hf = __bfloat1622float2(h2);
    __nv_bfloat162 l2 = __float22bfloat162_rn(make_float2(x.x - hf.x, x.y - hf.y));
    h = *reinterpret_cast<uint32_t*>(&h2);
    l = *reinterpret_cast<uint32_t*>(&l2);
}
__device__ __forceinline__ void split4w(const float4& x, uint2& hv, uint2& lv) {
    split2(make_float2(x.x, x.y), hv.x, lv.x);
    split2(make_float2(x.z, x.w), hv.y, lv.y);
}

__global__ void __launch_bounds__(256)
gemm_mma_kernel(const float* __restrict__ W, const float* __restrict__ ci,
                float* __restrict__ out, int N) {
    __shared__ __align__(128) char smem[16384];   // WHI [0,8K), WLO [8K,16K)
    uint32_t sb = smem_u32(smem);
    int tid = threadIdx.x, w = tid >> 5, lane = tid & 31;
    int row0 = blockIdx.x * 128;

    // ---- convert W -> bf16 hi/lo, swizzled 16B chunks (512 chunks) ----
    #pragma unroll
    for (int i = tid; i < 512; i += 256) {
        int f = i >> 3, c = i & 7;
        const float4* wp = reinterpret_cast<const float4*>(W) + f * 16 + c * 2;
        float4 x0 = wp[0], x1 = wp[1];
        uint2 h0, l0, h1, l1;
        split4w(x0, h0, l0);
        split4w(x1, h1, l1);
        uint32_t off = (uint32_t)f * 128 + (uint32_t)((c ^ (f & 7)) << 4);
        *reinterpret_cast<uint4*>(smem + off)        = make_uint4(h0.x, h0.y, h1.x, h1.y);
        *reinterpret_cast<uint4*>(smem + 8192 + off) = make_uint4(l0.x, l0.y, l1.x, l1.y);
    }
    __syncthreads();

    // A fragment coordinates (m16n8k16 row-major A):
    // thread owns rows grp, grp+8; k-pair kin, kin+8 within each 16-wide slab
    int grp = lane >> 2;
    int kin = (lane & 3) * 2;
    int rA = row0 + w * 16 + grp;
    int rB = rA + 8;
    bool okA = rA < N, okB = rB < N;
    const float* gA = &g_scratch[(size_t)rA * D];
    const float* gB = &g_scratch[(size_t)rB * D];

    // B ldmatrix.x2 lane plan (round-12 proven): lanes 0-7 octet rows k-lo,
    // 8-15 same rows k-hi (lanes 16-31 unused for address gen)
    int bi = lane & 7;
    int bkp = (lane >> 3) & 1;

    float acc[8][4];
    #pragma unroll
    for (int nb = 0; nb < 8; nb++)
        #pragma unroll
        for (int j = 0; j < 4; j++) acc[nb][j] = 0.f;

    #pragma unroll
    for (int kc = 0; kc < 4; kc++) {
        int k0 = kc * 16 + kin;
        float2 z = make_float2(0.f, 0.f);
        float2 x00 = okA ? *reinterpret_cast<const float2*>(gA + k0)     : z;
        float2 x10 = okB ? *reinterpret_cast<const float2*>(gB + k0)     : z;
        float2 x01 = okA ? *reinterpret_cast<const float2*>(gA + k0 + 8) : z;
        float2 x11 = okB ? *reinterpret_cast<const float2*>(gB + k0 + 8) : z;
        uint32_t AH[4], AL[4];
        split2(x00, AH[0], AL[0]);
        split2(x10, AH[1], AL[1]);
        split2(x01, AH[2], AL[2]);
        split2(x11, AH[3], AL[3]);

        #pragma unroll
        for (int nb = 0; nb < 8; nb++) {
            int n = nb * 8 + bi;
            uint32_t chunk = (uint32_t)(2 * kc + bkp);
            uint32_t boff = (uint32_t)n * 128 + ((chunk ^ (uint32_t)(n & 7)) << 4);
            uint32_t bh0, bh1, bl0, bl1;
            ldsm_x2(bh0, bh1, sb + boff);
            ldsm_x2(bl0, bl1, sb + 8192 + boff);
            mma_bf16(acc[nb], AH, bh0, bh1);   // hi*hi
            mma_bf16(acc[nb], AH, bl0, bl1);   // hi*lo
            mma_bf16(acc[nb], AL, bh0, bh1);   // lo*hi
        }
    }

    // ---- epilogue: scale by ci[row], float2 stores ----
    int group = lane >> 2, tig = lane & 3;
    int erA = row0 + w * 16 + group;
    int erB = erA + 8;
    float cA = (erA < N) ? ci[erA] : 0.f;
    float cB = (erB < N) ? ci[erB] : 0.f;
    #pragma unroll
    for (int nb = 0; nb < 8; nb++) {
        int col = nb * 8 + 2 * tig;
        if (erA < N) {
            float2 v = make_float2(acc[nb][0] * cA, acc[nb][1] * cA);
            *reinterpret_cast<float2*>(&out[(size_t)erA * D + col]) = v;
        }
        if (erB < N) {
            float2 v = make_float2(acc[nb][2] * cB, acc[nb][3] * cB);
            *reinterpret_cast<float2*>(&out[(size_t)erB * D + col]) = v;
        }
    }
}

// ---------------------------------------------------------------------------
// Launch
// Inputs: review_feat [E,64] f32, ci [N,1] f32, W [64,64] f32,
//         drop_mask [E,1] f32, src [E] i32, dst [E] i32.  Output: [N,64] f32
// ---------------------------------------------------------------------------
extern "C" void kernel_launch(void* const* d_in, const int* in_sizes, int n_in,
                              void* d_out, int out_size) {
    const float4* rf  = (const float4*)d_in[0];
    const float*  ci  = (const float*) d_in[1];
    const float*  W   = (const float*) d_in[2];
    const float*  dm  = (const float*) d_in[3];
    const int*    src = (const int*)   d_in[4];
    const int*    dst = (const int*)   d_in[5];
    float* out = (float*)d_out;

    int E = in_sizes[4];
    int N = in_sizes[1];

    // 1. zero scratch accumulator (graph-capturable memset node)
    void* gptr = nullptr;
    cudaGetSymbolAddress(&gptr, g_scratch);
    cudaMemsetAsync(gptr, 0, (size_t)N * D * sizeof(float), 0);

    // 2. warp-cooperative scatter-accumulate (dropout-sparse, REDG.v4)
    int warps = (E + 31) / 32;
    int sblocks = (warps * 32 + 255) / 256;
    scatter_kernel<<<sblocks, 256>>>(rf, ci, dm, src, dst, E);

    // 3. HMMA GEMM (bf16 3-pass split, direct-LDG A path) + ci scale
    int gblocks = (N + 127) / 128;
    gemm_mma_kernel<<<gblocks, 256>>>(W, ci, out, N);
}